// round 12
// baseline (speedup 1.0000x reference)
#include <cuda_runtime.h>
#include <cstdint>

// TopologyTracker: 64x64 histogram of (prev, curr) transitions over 16.7M events.
// Output layout (float32): [0..4095] = transitions + counts, [4096] = total + N.
//
// R12: single kernel, no memset / init node. Hist core = R11's floor-bound
// config (296x512, 2 CTAs/SM, 16 ev/iter, 8 front-batched LDG.128). Epilogue:
//   1) staggered REDG flush of smem hist -> g_acc (int)
//   2) sense-reversing software grid barrier (all 296 CTAs co-resident:
//      2/SM x 148 SMs, regs<=64, smem 16KB; spinners watch only the flag,
//      last arriver resets the counter then flips the flag -> replay-safe)
//   3) finalize spread across CTAs: 14 bins/CTA, plain STG
//      out = trans_in + g_acc, g_acc re-zeroed (induction).
// Out is fully overwritten each call -> deterministic under graph replay.

#define NUM_TILES 64
#define NUM_BINS  (NUM_TILES * NUM_TILES)   // 4096
#define THREADS   512
#define GRID      296                        // 2 CTAs/SM * 148 SMs
#define BINS_PER_CTA 14                      // 296*14 = 4144 >= 4097

__device__ int                   g_acc[NUM_BINS];   // zero-init; re-zeroed each call
__device__ unsigned int          g_cnt;             // barrier counter (returns to 0)
__device__ volatile unsigned int g_flag;            // barrier sense (toggles per call)

__global__ void __launch_bounds__(THREADS, 2)
tt_hist(const int* __restrict__ prev,
        const int* __restrict__ curr,
        const float* __restrict__ trans_in,
        const float* __restrict__ total_in,
        float* __restrict__ out,
        int out_size,
        int n)
{
    __shared__ int h[NUM_BINS];

    // Read barrier sense BEFORE arriving (flip only happens after all 296
    // CTAs have arrived, so this read is always the pre-flip value).
    const unsigned int sense = g_flag;

    #pragma unroll
    for (int i = threadIdx.x; i < NUM_BINS; i += THREADS) {
        h[i] = 0;
    }
    __syncthreads();

    const int tid    = blockIdx.x * THREADS + threadIdx.x;
    const int stride = gridDim.x * THREADS;

    const int4* __restrict__ p4 = reinterpret_cast<const int4*>(prev);
    const int4* __restrict__ c4 = reinterpret_cast<const int4*>(curr);

    // 16 events per iteration: 8 front-batched 16B loads (4 per stream).
    const int n16 = n >> 4;
    for (int i = tid; i < n16; i += stride) {
        int4 pa = p4[4 * i];
        int4 pb = p4[4 * i + 1];
        int4 pc = p4[4 * i + 2];
        int4 pd = p4[4 * i + 3];
        int4 ca = c4[4 * i];
        int4 cb = c4[4 * i + 1];
        int4 cc = c4[4 * i + 2];
        int4 cd = c4[4 * i + 3];

        atomicAdd(&h[(pa.x << 6) + ca.x], 1);
        atomicAdd(&h[(pa.y << 6) + ca.y], 1);
        atomicAdd(&h[(pa.z << 6) + ca.z], 1);
        atomicAdd(&h[(pa.w << 6) + ca.w], 1);
        atomicAdd(&h[(pb.x << 6) + cb.x], 1);
        atomicAdd(&h[(pb.y << 6) + cb.y], 1);
        atomicAdd(&h[(pb.z << 6) + cb.z], 1);
        atomicAdd(&h[(pb.w << 6) + cb.w], 1);
        atomicAdd(&h[(pc.x << 6) + cc.x], 1);
        atomicAdd(&h[(pc.y << 6) + cc.y], 1);
        atomicAdd(&h[(pc.z << 6) + cc.z], 1);
        atomicAdd(&h[(pc.w << 6) + cc.w], 1);
        atomicAdd(&h[(pd.x << 6) + cd.x], 1);
        atomicAdd(&h[(pd.y << 6) + cd.y], 1);
        atomicAdd(&h[(pd.z << 6) + cd.z], 1);
        atomicAdd(&h[(pd.w << 6) + cd.w], 1);
    }

    // Scalar tail (n % 16; N = 16777216 divisible, kept for safety).
    for (int i = (n16 << 4) + tid; i < n; i += stride) {
        atomicAdd(&h[(prev[i] << 6) + curr[i]], 1);
    }

    __syncthreads();

    // Flush smem hist -> g_acc (int REDG), staggered start per CTA so
    // concurrent CTAs hit different 128B L2 lines.
    const int off = (blockIdx.x << 5) & (NUM_BINS - 1);
    #pragma unroll
    for (int j = threadIdx.x; j < NUM_BINS; j += THREADS) {
        int i = (j + off) & (NUM_BINS - 1);
        int v = h[i];
        if (v != 0) {
            atomicAdd(&g_acc[i], v);
        }
    }

    // ---- grid barrier (sense-reversing) ----
    __threadfence();                 // release the flush
    __syncthreads();
    if (threadIdx.x == 0) {
        unsigned int t = atomicAdd(&g_cnt, 1u);
        if (t == (unsigned int)(GRID - 1)) {
            g_cnt = 0;               // reset counter before release
            __threadfence();
            g_flag = sense ^ 1u;     // release all spinners
        } else {
            while (g_flag == sense) { }
        }
    }
    __syncthreads();
    __threadfence();                 // acquire g_acc writes from all CTAs

    // ---- finalize: this CTA owns BINS_PER_CTA bins; plain stores ----
    {
        int bin = blockIdx.x * BINS_PER_CTA + threadIdx.x;
        if (threadIdx.x < BINS_PER_CTA && bin <= NUM_BINS) {
            if (bin < NUM_BINS) {
                if (bin < out_size) {
                    out[bin] = trans_in[bin] + (float)g_acc[bin];
                }
                g_acc[bin] = 0;      // reset for next call
            } else if (bin < out_size) {   // bin == NUM_BINS: the total
                out[NUM_BINS] = total_in[0] + (float)n;
            }
        }
    }
}

// ---------------------------------------------------------------------------
// Launcher: one kernel, no auxiliary nodes.
// ---------------------------------------------------------------------------
extern "C" void kernel_launch(void* const* d_in, const int* in_sizes, int n_in,
                              void* d_out, int out_size)
{
    const int*   prev     = (const int*)  d_in[0];
    const int*   curr     = (const int*)  d_in[1];
    const float* trans_in = (const float*)d_in[2];
    const float* total_in = (const float*)d_in[3];
    float*       out      = (float*)d_out;

    const int n = in_sizes[0];

    tt_hist<<<GRID, THREADS>>>(prev, curr, trans_in, total_in, out,
                               out_size, n);
}